// round 12
// baseline (speedup 1.0000x reference)
#include <cuda_runtime.h>
#include <cuda_bf16.h>
#include <cstdint>

// B=32, W=256, N=512, thresholds {0.3,0.5,0.7}
// out: (B,6) fp32 [t0_b0,t0_b1,t1_b0,t1_b1,t2_b0,t2_b1]

#define BATCH 32
#define WIN   256
#define NA    512
#define CAP   131072   // >= 512*511/2
#define KCH   64       // bf16 per K-chunk (128 B rows)
#define NCH   4        // K = 256 (h.h only; band+fixup covers the bf16 error)
#define NSTG  3
#define STAGE_BYTES 24576   // 16KB A(128 rows) + 8KB B(64 rows)
#define SMEM_DYN    (NSTG * STAGE_BYTES)
#define NTILE 20
#define BAND  4.5e-3f       // certified |corr_exact - corr_hh| bound is 3.9e-3
#define SCAP  32768

// ---------------- device scratch ----------------
__device__ __nv_bfloat16 g_h[BATCH][NA][WIN];   // 8 MB
__device__ int   g_ecnt[3][BATCH];
__device__ unsigned int g_edges[3][BATCH][CAP];
__device__ int   g_scnt;
__device__ unsigned int g_susp[SCAP];   // (mask<<23)|(b<<18)|(gi<<9)|gj

__device__ __forceinline__ uint32_t smem_u32(const void* p) {
    uint32_t a;
    asm("{ .reg .u64 t; cvta.to.shared.u64 t, %1; cvt.u32.u64 %0, t; }" : "=r"(a) : "l"(p));
    return a;
}
#define SW128(x) ((x) ^ (((x) >> 3) & 0x70))
#define CP16(dst, src) \
    asm volatile("cp.async.cg.shared.global [%0], [%1], 16;" :: "r"(dst), "l"(src))
#define CPCOMMIT() asm volatile("cp.async.commit_group;" ::: "memory")
#define CPWAIT1()  asm volatile("cp.async.wait_group 1;" ::: "memory")
#define CPWAIT0()  asm volatile("cp.async.wait_group 0;" ::: "memory")

// ------- fused stats + normalize + bf16(h) + transpose -------
// CTA: 32 assets x 256 w. grid (16, 32). 256 threads.
// fsm bank-swizzle: value (w, a) lives at fsm[w][(a + (w&31) + 4*(w>>5)) & 31].
__global__ void __launch_bounds__(256)
convert_kernel(const float* __restrict__ ret) {
    __shared__ float fsm[WIN][32];              // 32 KB, swizzled
    __shared__ float ps[8][32], ps2[8][32], mean_s[32], inv_s[32];

    const int b = blockIdx.y, n0 = blockIdx.x * 32;
    const int t = threadIdx.x;

    if (blockIdx.x == 0 && b == 0) {
        if (t < 96) ((int*)g_ecnt)[t] = 0;
        if (t == 96) g_scnt = 0;
    }

    // phase 0: load 256 w-rows x 32 assets, float4 per thread (8 iters)
    const float* src = ret + (size_t)b * WIN * NA + n0;
#pragma unroll
    for (int it = 0; it < 8; it++) {
        int idx = t + it * 256;
        int w = idx >> 3, sg = idx & 7;
        float4 v4 = *(const float4*)(src + (size_t)w * NA + sg * 4);
        int cb = sg * 4 + (w & 31) + 4 * (w >> 5);
        fsm[w][(cb + 0) & 31] = v4.x;
        fsm[w][(cb + 1) & 31] = v4.y;
        fsm[w][(cb + 2) & 31] = v4.z;
        fsm[w][(cb + 3) & 31] = v4.w;
    }
    __syncthreads();

    // phase 1: per-(asset, 32-w chunk) partials, w ascending (order preserved)
    {
        const int a = t & 31, q = t >> 5;
        float s = 0.f, s2 = 0.f;
#pragma unroll
        for (int i = 0; i < 32; i++) {
            float x = fsm[q * 32 + i][(a + i + 4 * q) & 31];
            s += x; s2 += x * x;
        }
        ps[q][a] = s; ps2[q][a] = s2;
    }
    __syncthreads();

    // phase 2: combine partials (fixed order), stats
    if ((t >> 5) == 0) {
        const int a = t & 31;
        float ss = 0.f, ss2 = 0.f;
#pragma unroll
        for (int k = 0; k < 8; k++) { ss += ps[k][a]; ss2 += ps2[k][a]; }
        float mean = ss * (1.0f / WIN);
        float var = fmaxf((ss2 - ss * mean) * (1.0f / (WIN - 1)), 0.0f);
        mean_s[a] = mean;
        inv_s[a] = 1.0f / (sqrtf(var) + 1e-8f);
    }
    __syncthreads();

    // phase 3: remap (asset = t>>3, seg = t&7) -> coalesced 512B/row warp stores
    {
        const int a2 = t >> 3, q2 = t & 7;
        const float mean = mean_s[a2], inv = inv_s[a2];
        __nv_bfloat16* dh = &g_h[b][n0 + a2][q2 * 32];
#pragma unroll
        for (int i8 = 0; i8 < 32; i8 += 8) {
            unsigned int hw[4];
#pragma unroll
            for (int k = 0; k < 4; k++) {
                int i = i8 + 2 * k;                 // w & 31 (since q2*32 aligned)
                int w = q2 * 32 + i;
                float x0 = (fsm[w][(a2 + i + 4 * q2) & 31] - mean) * inv;
                float x1 = (fsm[w + 1][(a2 + i + 1 + 4 * q2) & 31] - mean) * inv;
                __nv_bfloat16 h0 = __float2bfloat16(x0);
                __nv_bfloat16 h1 = __float2bfloat16(x1);
                hw[k] = ((unsigned int)__bfloat16_as_ushort(h1) << 16)
                      | __bfloat16_as_ushort(h0);
            }
            *(uint4*)(dh + i8) = make_uint4(hw[0], hw[1], hw[2], hw[3]);
        }
    }
}

// ---------------- corr GEMM: h.h via mma.sync bf16, K=256, 3-stage cp.async --
// CTA tile 128x64, 8 warps (4x2), warp tile 32x32. Grid: 20 upper-tri tiles x 32 b.
__global__ void __launch_bounds__(256, 3)
corr_mma_kernel() {
    extern __shared__ __align__(128) unsigned char dsm[];
    const uint32_t sb = smem_u32(dsm);

    const int TI[NTILE] = {0,0,0,0,0,0,0,0, 1,1,1,1,1,1, 2,2,2,2, 3,3};
    const int TJ[NTILE] = {0,1,2,3,4,5,6,7, 2,3,4,5,6,7, 4,5,6,7, 6,7};
    const int b  = blockIdx.y;
    const int i0 = TI[blockIdx.x] * 128;
    const int j0 = TJ[blockIdx.x] * 64;
    const int t = threadIdx.x;
    const int wid = t >> 5, lane = t & 31;
    const int mw = wid >> 1;       // 0..3 : 32-row group
    const int nw = wid & 1;        // 0..1 : 32-col group

    float acc[2][4][4];
#pragma unroll
    for (int mt = 0; mt < 2; mt++)
#pragma unroll
        for (int nt = 0; nt < 4; nt++)
#pragma unroll
            for (int q = 0; q < 4; q++) acc[mt][nt][q] = 0.f;

    const int arow = t >> 1, ahalf = t & 1;
    const uint32_t aswz = SW128(arow * 128 + ahalf * 64);
    const int brow = t >> 2, bq = t & 3;
    const uint32_t bswz = SW128(brow * 128 + bq * 32);

    const __nv_bfloat16* rowA = &g_h[b][i0 + arow][0];
    const __nv_bfloat16* rowB = &g_h[b][j0 + brow][0];

    auto load_chunk = [&](int c) {
        const uint32_t base = sb + (c % NSTG) * STAGE_BYTES;
        const __nv_bfloat16* sA = rowA + c * KCH + ahalf * 32;
#pragma unroll
        for (int f = 0; f < 4; f++)
            CP16(base + (aswz ^ (f * 16)), sA + f * 8);
        const __nv_bfloat16* sB = rowB + c * KCH + bq * 16;
        CP16(base + 16384 + bswz, sB);
        CP16(base + 16384 + (bswz ^ 16), sB + 8);
        CPCOMMIT();
    };

    load_chunk(0);
    load_chunk(1);

    for (int c = 0; c < NCH; c++) {
        if (c < NCH - 1) CPWAIT1(); else CPWAIT0();
        __syncthreads();

        const uint32_t sbA = sb + (c % NSTG) * STAGE_BYTES;
        const uint32_t sbB = sbA + 16384;
#pragma unroll
        for (int ks = 0; ks < 4; ks++) {
            const int kb = ks * 32;
            uint32_t af[2][4];
#pragma unroll
            for (int mt = 0; mt < 2; mt++) {
                int row = mw * 32 + mt * 16 + ((lane >> 3) & 1) * 8 + (lane & 7);
                int kbyte = kb + (lane >> 4) * 16;
                uint32_t addr = sbA + SW128(row * 128 + kbyte);
                asm volatile("ldmatrix.sync.aligned.m8n8.x4.shared.b16 {%0,%1,%2,%3}, [%4];"
                    : "=r"(af[mt][0]), "=r"(af[mt][1]), "=r"(af[mt][2]), "=r"(af[mt][3])
                    : "r"(addr));
            }
            uint32_t bf[4][2];
#pragma unroll
            for (int np = 0; np < 2; np++) {
                int row = nw * 32 + np * 16 + ((lane >> 4) & 1) * 8 + (lane & 7);
                int kbyte = kb + ((lane >> 3) & 1) * 16;
                uint32_t addr = sbB + SW128(row * 128 + kbyte);
                asm volatile("ldmatrix.sync.aligned.m8n8.x4.shared.b16 {%0,%1,%2,%3}, [%4];"
                    : "=r"(bf[2*np][0]), "=r"(bf[2*np][1]),
                      "=r"(bf[2*np+1][0]), "=r"(bf[2*np+1][1])
                    : "r"(addr));
            }
#pragma unroll
            for (int mt = 0; mt < 2; mt++)
#pragma unroll
                for (int nt = 0; nt < 4; nt++)
                    asm volatile(
                        "mma.sync.aligned.m16n8k16.row.col.f32.bf16.bf16.f32 "
                        "{%0,%1,%2,%3}, {%4,%5,%6,%7}, {%8,%9}, {%0,%1,%2,%3};"
                        : "+f"(acc[mt][nt][0]), "+f"(acc[mt][nt][1]),
                          "+f"(acc[mt][nt][2]), "+f"(acc[mt][nt][3])
                        : "r"(af[mt][0]), "r"(af[mt][1]), "r"(af[mt][2]), "r"(af[mt][3]),
                          "r"(bf[nt][0]), "r"(bf[nt][1]));
        }

        if (c + 2 < NCH) load_chunk(c + 2);
        else CPCOMMIT();   // keep group accounting uniform
    }

    // epilogue: banded threshold -> edges / suspects
    const float TH[3] = {0.3f, 0.5f, 0.7f};
#pragma unroll
    for (int mt = 0; mt < 2; mt++) {
#pragma unroll
        for (int nt = 0; nt < 4; nt++) {
            int gi0 = i0 + mw * 32 + mt * 16 + (lane >> 2);
            int gj0 = j0 + nw * 32 + nt * 8 + 2 * (lane & 3);
#pragma unroll
            for (int q = 0; q < 4; q++) {
                int gi = gi0 + (q >> 1) * 8;
                int gj = gj0 + (q & 1);
                float v = fabsf(acc[mt][nt][q] * (1.0f / 256.0f));
                if (gi < gj && v > TH[0] - BAND) {
                    unsigned int e = ((unsigned int)gi << 16) | (unsigned int)gj;
                    unsigned int mask = 0;
#pragma unroll
                    for (int k = 0; k < 3; k++) {
                        if (v > TH[k] + BAND) {
                            int p = atomicAdd(&g_ecnt[k][b], 1);
                            g_edges[k][b][p] = e;
                        } else if (v > TH[k] - BAND) {
                            mask |= 1u << k;
                        }
                    }
                    if (mask) {
                        int p = atomicAdd(&g_scnt, 1);
                        if (p < SCAP)
                            g_susp[p] = (mask << 23) | ((unsigned int)b << 18)
                                      | ((unsigned int)gi << 9) | (unsigned int)gj;
                    }
                }
            }
        }
    }
}

// ------- components + Betti, with in-block fp64 fixup of in-band suspects ----
__global__ void __launch_bounds__(512, 1)
betti_kernel(const float* __restrict__ ret, float* __restrict__ out) {
    __shared__ int label[NA];
    __shared__ int changed;
    __shared__ int comp_cnt;
    __shared__ unsigned int extra[512];
    __shared__ int extra_cnt;
    __shared__ double wsum[8][5];

    const int tt = blockIdx.x >> 5;
    const int b  = blockIdx.x & 31;
    const int tid = threadIdx.x;

    const int cnt = g_ecnt[tt][b];
    const unsigned int* el = &g_edges[tt][b][0];

    label[tid] = tid;
    if (tid == 0) { comp_cnt = 0; extra_cnt = 0; }
    __syncthreads();

    // resolve suspects for this (tt, b) with exact fp64 correlation
    const int scnt = min(g_scnt, SCAP);
    const double THD[3] = {0.3, 0.5, 0.7};
    for (int s = 0; s < scnt; s++) {
        unsigned int wd = g_susp[s];
        if ((((wd >> 18) & 31) != (unsigned)b) || !((wd >> 23) & (1u << tt)))
            continue;
        int gj = wd & 511, gi = (wd >> 9) & 511;

        double p0 = 0, p1 = 0, p2 = 0, p3 = 0, p4 = 0;
        if (tid < WIN) {
            double xi = (double)ret[((size_t)b * WIN + tid) * NA + gi];
            double xj = (double)ret[((size_t)b * WIN + tid) * NA + gj];
            p0 = xi; p1 = xi * xi; p2 = xj; p3 = xj * xj; p4 = xi * xj;
        }
#pragma unroll
        for (int o = 16; o; o >>= 1) {
            p0 += __shfl_down_sync(0xFFFFFFFFu, p0, o);
            p1 += __shfl_down_sync(0xFFFFFFFFu, p1, o);
            p2 += __shfl_down_sync(0xFFFFFFFFu, p2, o);
            p3 += __shfl_down_sync(0xFFFFFFFFu, p3, o);
            p4 += __shfl_down_sync(0xFFFFFFFFu, p4, o);
        }
        if (tid < WIN && (tid & 31) == 0) {
            wsum[tid >> 5][0] = p0; wsum[tid >> 5][1] = p1;
            wsum[tid >> 5][2] = p2; wsum[tid >> 5][3] = p3;
            wsum[tid >> 5][4] = p4;
        }
        __syncthreads();
        if (tid == 0) {
            double r0 = 0, r1 = 0, r2 = 0, r3 = 0, r4 = 0;
#pragma unroll
            for (int k = 0; k < 8; k++) {
                r0 += wsum[k][0]; r1 += wsum[k][1]; r2 += wsum[k][2];
                r3 += wsum[k][3]; r4 += wsum[k][4];
            }
            double mi = r0 / 256.0, mj = r2 / 256.0;
            double vi = (r1 - r0 * mi) / 255.0;
            double vj = (r3 - r2 * mj) / 255.0;
            double di = sqrt(vi > 0 ? vi : 0) + 1e-8;
            double dj = sqrt(vj > 0 ? vj : 0) + 1e-8;
            double cov = r4 - 256.0 * mi * mj;
            double v = fabs(cov / (di * dj) / 256.0);
            if (v > THD[tt] && extra_cnt < 512)
                extra[extra_cnt++] = ((unsigned int)gi << 16) | (unsigned int)gj;
        }
        __syncthreads();
    }

    // min-label propagation over main + extra edge lists
    while (true) {
        __syncthreads();
        if (tid == 0) changed = 0;
        __syncthreads();
        for (int e = tid; e < cnt; e += NA) {
            unsigned int pk = el[e];
            int i = pk >> 16, j = pk & 0xFFFF;
            int li = label[i], lj = label[j];
            if (li < lj) { atomicMin(&label[j], li); changed = 1; }
            else if (lj < li) { atomicMin(&label[i], lj); changed = 1; }
        }
        for (int e = tid; e < extra_cnt; e += NA) {
            unsigned int pk = extra[e];
            int i = pk >> 16, j = pk & 0xFFFF;
            int li = label[i], lj = label[j];
            if (li < lj) { atomicMin(&label[j], li); changed = 1; }
            else if (lj < li) { atomicMin(&label[i], lj); changed = 1; }
        }
        __syncthreads();
        int l = label[tid];
        int ll = label[l];
        if (ll < l) { label[tid] = ll; changed = 1; }
        __syncthreads();
        if (!changed) break;
    }

    int isrep = (label[tid] == tid) ? 1 : 0;
#pragma unroll
    for (int o = 16; o; o >>= 1) isrep += __shfl_down_sync(0xFFFFFFFFu, isrep, o);
    if ((tid & 31) == 0) atomicAdd(&comp_cnt, isrep);
    __syncthreads();

    if (tid == 0) {
        float comp = (float)comp_cnt;
        float edges = (float)(cnt + extra_cnt);
        float b1 = fmaxf(0.0f, edges - (float)NA + comp);
        out[b * 6 + tt * 2 + 0] = comp * (1.0f / NA);
        out[b * 6 + tt * 2 + 1] = b1 * (1.0f / NA);
    }
}

// ---------------- launch ----------------
extern "C" void kernel_launch(void* const* d_in, const int* in_sizes, int n_in,
                              void* d_out, int out_size) {
    const float* ret = (const float*)d_in[0];
    float* out = (float*)d_out;
    (void)in_sizes; (void)n_in; (void)out_size;

    cudaFuncSetAttribute(corr_mma_kernel,
                         cudaFuncAttributeMaxDynamicSharedMemorySize, SMEM_DYN);

    { dim3 g(NA / 32, BATCH); convert_kernel<<<g, 256>>>(ret); }
    { dim3 g(NTILE, BATCH);   corr_mma_kernel<<<g, 256, SMEM_DYN>>>(); }
    betti_kernel<<<96, 512>>>(ret, out);
}

// round 13
// speedup vs baseline: 1.0570x; 1.0570x over previous
#include <cuda_runtime.h>
#include <cuda_bf16.h>
#include <cstdint>

// B=32, W=256, N=512, thresholds {0.3,0.5,0.7}
// out: (B,6) fp32 [t0_b0,t0_b1,t1_b0,t1_b1,t2_b0,t2_b1]

#define BATCH 32
#define WIN   256
#define NA    512
#define CAP   131072   // >= 512*511/2
#define KCH   64       // bf16 per K-chunk (128 B rows)
#define NCH   4        // K = 256 (h.h only; band+fixup covers the bf16 error)
#define NSTG  3
#define STAGE_BYTES 24576   // 16KB A(128 rows) + 8KB B(64 rows)
#define SMEM_DYN    (NSTG * STAGE_BYTES)
#define NTILE 20
#define BAND  4.5e-3f       // certified |corr_exact - corr_hh| bound is 3.9e-3
#define SCAP  32768

// ---------------- device scratch ----------------
__device__ __nv_bfloat16 g_h[BATCH][NA][WIN];   // 8 MB
__device__ int   g_ecnt[3][BATCH];
__device__ unsigned int g_edges[3][BATCH][CAP];
__device__ int   g_scnt;
__device__ unsigned int g_susp[SCAP];   // (mask<<23)|(b<<18)|(gi<<9)|gj

__device__ __forceinline__ uint32_t smem_u32(const void* p) {
    uint32_t a;
    asm("{ .reg .u64 t; cvta.to.shared.u64 t, %1; cvt.u32.u64 %0, t; }" : "=r"(a) : "l"(p));
    return a;
}
#define SW128(x) ((x) ^ (((x) >> 3) & 0x70))
#define CP16(dst, src) \
    asm volatile("cp.async.cg.shared.global [%0], [%1], 16;" :: "r"(dst), "l"(src))
#define CPCOMMIT() asm volatile("cp.async.commit_group;" ::: "memory")
#define CPWAIT1()  asm volatile("cp.async.wait_group 1;" ::: "memory")
#define CPWAIT0()  asm volatile("cp.async.wait_group 0;" ::: "memory")

// ------- fused stats + normalize + bf16(h) + transpose -------
// CTA: 32 assets x 256 w. grid (16, 32). 512 threads.
// fsm bank-swizzle: value (w, a) lives at fsm[w][(a + (w&31) + 4*(w>>5)) & 31].
__global__ void __launch_bounds__(512)
convert_kernel(const float* __restrict__ ret) {
    __shared__ float fsm[WIN][32];              // 32 KB, swizzled
    __shared__ float ps[16][32], ps2[16][32], mean_s[32], inv_s[32];

    const int b = blockIdx.y, n0 = blockIdx.x * 32;
    const int t = threadIdx.x;

    if (blockIdx.x == 0 && b == 0) {
        if (t < 96) ((int*)g_ecnt)[t] = 0;
        if (t == 96) g_scnt = 0;
    }

    // phase 0: load 256 w-rows x 32 assets, float4 per thread (4 iters)
    const float* src = ret + (size_t)b * WIN * NA + n0;
#pragma unroll
    for (int it = 0; it < 4; it++) {
        int idx = t + it * 512;
        int w = idx >> 3, sg = idx & 7;
        float4 v4 = *(const float4*)(src + (size_t)w * NA + sg * 4);
        int cb = sg * 4 + (w & 31) + 4 * (w >> 5);
        fsm[w][(cb + 0) & 31] = v4.x;
        fsm[w][(cb + 1) & 31] = v4.y;
        fsm[w][(cb + 2) & 31] = v4.z;
        fsm[w][(cb + 3) & 31] = v4.w;
    }
    __syncthreads();

    // phase 1: per-(asset, 16-w chunk) partials, w ascending within chunk
    {
        const int a = t & 31, q = t >> 5;       // q: 0..15
        float s = 0.f, s2 = 0.f;
#pragma unroll
        for (int i = 0; i < 16; i++) {
            int w = q * 16 + i;
            float x = fsm[w][(a + (w & 31) + 4 * (w >> 5)) & 31];
            s += x; s2 += x * x;
        }
        ps[q][a] = s; ps2[q][a] = s2;
    }
    __syncthreads();

    // phase 2: combine partials (fixed ascending order), stats
    if ((t >> 5) == 0) {
        const int a = t & 31;
        float ss = 0.f, ss2 = 0.f;
#pragma unroll
        for (int k = 0; k < 16; k++) { ss += ps[k][a]; ss2 += ps2[k][a]; }
        float mean = ss * (1.0f / WIN);
        float var = fmaxf((ss2 - ss * mean) * (1.0f / (WIN - 1)), 0.0f);
        mean_s[a] = mean;
        inv_s[a] = 1.0f / (sqrtf(var) + 1e-8f);
    }
    __syncthreads();

    // phase 3: asset = t>>4, seg = t&15 -> 16 w per thread, coalesced stores
    {
        const int a2 = t >> 4, q2 = t & 15;
        const float mean = mean_s[a2], inv = inv_s[a2];
        __nv_bfloat16* dh = &g_h[b][n0 + a2][q2 * 16];
        unsigned int hw[8];
#pragma unroll
        for (int k = 0; k < 8; k++) {
            int w = q2 * 16 + 2 * k;
            float x0 = (fsm[w][(a2 + (w & 31) + 4 * (w >> 5)) & 31] - mean) * inv;
            int w1 = w + 1;
            float x1 = (fsm[w1][(a2 + (w1 & 31) + 4 * (w1 >> 5)) & 31] - mean) * inv;
            __nv_bfloat16 h0 = __float2bfloat16(x0);
            __nv_bfloat16 h1 = __float2bfloat16(x1);
            hw[k] = ((unsigned int)__bfloat16_as_ushort(h1) << 16)
                  | __bfloat16_as_ushort(h0);
        }
        *(uint4*)(dh + 0) = make_uint4(hw[0], hw[1], hw[2], hw[3]);
        *(uint4*)(dh + 8) = make_uint4(hw[4], hw[5], hw[6], hw[7]);
    }
}

// ---------------- corr GEMM: h.h via mma.sync bf16, K=256, 3-stage cp.async --
// CTA tile 128x64, 8 warps (4x2), warp tile 32x32. Grid: 20 upper-tri tiles x 32 b.
__global__ void __launch_bounds__(256, 3)
corr_mma_kernel() {
    extern __shared__ __align__(128) unsigned char dsm[];
    const uint32_t sb = smem_u32(dsm);

    const int TI[NTILE] = {0,0,0,0,0,0,0,0, 1,1,1,1,1,1, 2,2,2,2, 3,3};
    const int TJ[NTILE] = {0,1,2,3,4,5,6,7, 2,3,4,5,6,7, 4,5,6,7, 6,7};
    const int b  = blockIdx.y;
    const int i0 = TI[blockIdx.x] * 128;
    const int j0 = TJ[blockIdx.x] * 64;
    const int t = threadIdx.x;
    const int wid = t >> 5, lane = t & 31;
    const int mw = wid >> 1;       // 0..3 : 32-row group
    const int nw = wid & 1;        // 0..1 : 32-col group

    float acc[2][4][4];
#pragma unroll
    for (int mt = 0; mt < 2; mt++)
#pragma unroll
        for (int nt = 0; nt < 4; nt++)
#pragma unroll
            for (int q = 0; q < 4; q++) acc[mt][nt][q] = 0.f;

    const int arow = t >> 1, ahalf = t & 1;
    const uint32_t aswz = SW128(arow * 128 + ahalf * 64);
    const int brow = t >> 2, bq = t & 3;
    const uint32_t bswz = SW128(brow * 128 + bq * 32);

    const __nv_bfloat16* rowA = &g_h[b][i0 + arow][0];
    const __nv_bfloat16* rowB = &g_h[b][j0 + brow][0];

    auto load_chunk = [&](int c) {
        const uint32_t base = sb + (c % NSTG) * STAGE_BYTES;
        const __nv_bfloat16* sA = rowA + c * KCH + ahalf * 32;
#pragma unroll
        for (int f = 0; f < 4; f++)
            CP16(base + (aswz ^ (f * 16)), sA + f * 8);
        const __nv_bfloat16* sB = rowB + c * KCH + bq * 16;
        CP16(base + 16384 + bswz, sB);
        CP16(base + 16384 + (bswz ^ 16), sB + 8);
        CPCOMMIT();
    };

    load_chunk(0);
    load_chunk(1);

    for (int c = 0; c < NCH; c++) {
        if (c < NCH - 1) CPWAIT1(); else CPWAIT0();
        __syncthreads();

        const uint32_t sbA = sb + (c % NSTG) * STAGE_BYTES;
        const uint32_t sbB = sbA + 16384;
#pragma unroll
        for (int ks = 0; ks < 4; ks++) {
            const int kb = ks * 32;
            uint32_t af[2][4];
#pragma unroll
            for (int mt = 0; mt < 2; mt++) {
                int row = mw * 32 + mt * 16 + ((lane >> 3) & 1) * 8 + (lane & 7);
                int kbyte = kb + (lane >> 4) * 16;
                uint32_t addr = sbA + SW128(row * 128 + kbyte);
                asm volatile("ldmatrix.sync.aligned.m8n8.x4.shared.b16 {%0,%1,%2,%3}, [%4];"
                    : "=r"(af[mt][0]), "=r"(af[mt][1]), "=r"(af[mt][2]), "=r"(af[mt][3])
                    : "r"(addr));
            }
            uint32_t bf[4][2];
#pragma unroll
            for (int np = 0; np < 2; np++) {
                int row = nw * 32 + np * 16 + ((lane >> 4) & 1) * 8 + (lane & 7);
                int kbyte = kb + ((lane >> 3) & 1) * 16;
                uint32_t addr = sbB + SW128(row * 128 + kbyte);
                asm volatile("ldmatrix.sync.aligned.m8n8.x4.shared.b16 {%0,%1,%2,%3}, [%4];"
                    : "=r"(bf[2*np][0]), "=r"(bf[2*np][1]),
                      "=r"(bf[2*np+1][0]), "=r"(bf[2*np+1][1])
                    : "r"(addr));
            }
#pragma unroll
            for (int mt = 0; mt < 2; mt++)
#pragma unroll
                for (int nt = 0; nt < 4; nt++)
                    asm volatile(
                        "mma.sync.aligned.m16n8k16.row.col.f32.bf16.bf16.f32 "
                        "{%0,%1,%2,%3}, {%4,%5,%6,%7}, {%8,%9}, {%0,%1,%2,%3};"
                        : "+f"(acc[mt][nt][0]), "+f"(acc[mt][nt][1]),
                          "+f"(acc[mt][nt][2]), "+f"(acc[mt][nt][3])
                        : "r"(af[mt][0]), "r"(af[mt][1]), "r"(af[mt][2]), "r"(af[mt][3]),
                          "r"(bf[nt][0]), "r"(bf[nt][1]));
        }

        if (c + 2 < NCH) load_chunk(c + 2);
        else CPCOMMIT();   // keep group accounting uniform
    }

    // epilogue: banded threshold -> edges / suspects
    const float TH[3] = {0.3f, 0.5f, 0.7f};
#pragma unroll
    for (int mt = 0; mt < 2; mt++) {
#pragma unroll
        for (int nt = 0; nt < 4; nt++) {
            int gi0 = i0 + mw * 32 + mt * 16 + (lane >> 2);
            int gj0 = j0 + nw * 32 + nt * 8 + 2 * (lane & 3);
#pragma unroll
            for (int q = 0; q < 4; q++) {
                int gi = gi0 + (q >> 1) * 8;
                int gj = gj0 + (q & 1);
                float v = fabsf(acc[mt][nt][q] * (1.0f / 256.0f));
                if (gi < gj && v > TH[0] - BAND) {
                    unsigned int e = ((unsigned int)gi << 16) | (unsigned int)gj;
                    unsigned int mask = 0;
#pragma unroll
                    for (int k = 0; k < 3; k++) {
                        if (v > TH[k] + BAND) {
                            int p = atomicAdd(&g_ecnt[k][b], 1);
                            g_edges[k][b][p] = e;
                        } else if (v > TH[k] - BAND) {
                            mask |= 1u << k;
                        }
                    }
                    if (mask) {
                        int p = atomicAdd(&g_scnt, 1);
                        if (p < SCAP)
                            g_susp[p] = (mask << 23) | ((unsigned int)b << 18)
                                      | ((unsigned int)gi << 9) | (unsigned int)gj;
                    }
                }
            }
        }
    }
}

// ------- components + Betti, with in-block fp64 fixup of in-band suspects ----
__global__ void __launch_bounds__(512, 1)
betti_kernel(const float* __restrict__ ret, float* __restrict__ out) {
    __shared__ int label[NA];
    __shared__ int changed;
    __shared__ int comp_cnt;
    __shared__ unsigned int extra[512];
    __shared__ int extra_cnt;
    __shared__ double wsum[8][5];

    const int tt = blockIdx.x >> 5;
    const int b  = blockIdx.x & 31;
    const int tid = threadIdx.x;

    const int cnt = g_ecnt[tt][b];
    const unsigned int* el = &g_edges[tt][b][0];

    label[tid] = tid;
    if (tid == 0) { comp_cnt = 0; extra_cnt = 0; }
    __syncthreads();

    // resolve suspects for this (tt, b) with exact fp64 correlation
    const int scnt = min(g_scnt, SCAP);
    const double THD[3] = {0.3, 0.5, 0.7};
    for (int s = 0; s < scnt; s++) {
        unsigned int wd = g_susp[s];
        if ((((wd >> 18) & 31) != (unsigned)b) || !((wd >> 23) & (1u << tt)))
            continue;
        int gj = wd & 511, gi = (wd >> 9) & 511;

        double p0 = 0, p1 = 0, p2 = 0, p3 = 0, p4 = 0;
        if (tid < WIN) {
            double xi = (double)ret[((size_t)b * WIN + tid) * NA + gi];
            double xj = (double)ret[((size_t)b * WIN + tid) * NA + gj];
            p0 = xi; p1 = xi * xi; p2 = xj; p3 = xj * xj; p4 = xi * xj;
        }
#pragma unroll
        for (int o = 16; o; o >>= 1) {
            p0 += __shfl_down_sync(0xFFFFFFFFu, p0, o);
            p1 += __shfl_down_sync(0xFFFFFFFFu, p1, o);
            p2 += __shfl_down_sync(0xFFFFFFFFu, p2, o);
            p3 += __shfl_down_sync(0xFFFFFFFFu, p3, o);
            p4 += __shfl_down_sync(0xFFFFFFFFu, p4, o);
        }
        if (tid < WIN && (tid & 31) == 0) {
            wsum[tid >> 5][0] = p0; wsum[tid >> 5][1] = p1;
            wsum[tid >> 5][2] = p2; wsum[tid >> 5][3] = p3;
            wsum[tid >> 5][4] = p4;
        }
        __syncthreads();
        if (tid == 0) {
            double r0 = 0, r1 = 0, r2 = 0, r3 = 0, r4 = 0;
#pragma unroll
            for (int k = 0; k < 8; k++) {
                r0 += wsum[k][0]; r1 += wsum[k][1]; r2 += wsum[k][2];
                r3 += wsum[k][3]; r4 += wsum[k][4];
            }
            double mi = r0 / 256.0, mj = r2 / 256.0;
            double vi = (r1 - r0 * mi) / 255.0;
            double vj = (r3 - r2 * mj) / 255.0;
            double di = sqrt(vi > 0 ? vi : 0) + 1e-8;
            double dj = sqrt(vj > 0 ? vj : 0) + 1e-8;
            double cov = r4 - 256.0 * mi * mj;
            double v = fabs(cov / (di * dj) / 256.0);
            if (v > THD[tt] && extra_cnt < 512)
                extra[extra_cnt++] = ((unsigned int)gi << 16) | (unsigned int)gj;
        }
        __syncthreads();
    }

    // min-label propagation over main + extra edge lists
    while (true) {
        __syncthreads();
        if (tid == 0) changed = 0;
        __syncthreads();
        for (int e = tid; e < cnt; e += NA) {
            unsigned int pk = el[e];
            int i = pk >> 16, j = pk & 0xFFFF;
            int li = label[i], lj = label[j];
            if (li < lj) { atomicMin(&label[j], li); changed = 1; }
            else if (lj < li) { atomicMin(&label[i], lj); changed = 1; }
        }
        for (int e = tid; e < extra_cnt; e += NA) {
            unsigned int pk = extra[e];
            int i = pk >> 16, j = pk & 0xFFFF;
            int li = label[i], lj = label[j];
            if (li < lj) { atomicMin(&label[j], li); changed = 1; }
            else if (lj < li) { atomicMin(&label[i], lj); changed = 1; }
        }
        __syncthreads();
        int l = label[tid];
        int ll = label[l];
        if (ll < l) { label[tid] = ll; changed = 1; }
        __syncthreads();
        if (!changed) break;
    }

    int isrep = (label[tid] == tid) ? 1 : 0;
#pragma unroll
    for (int o = 16; o; o >>= 1) isrep += __shfl_down_sync(0xFFFFFFFFu, isrep, o);
    if ((tid & 31) == 0) atomicAdd(&comp_cnt, isrep);
    __syncthreads();

    if (tid == 0) {
        float comp = (float)comp_cnt;
        float edges = (float)(cnt + extra_cnt);
        float b1 = fmaxf(0.0f, edges - (float)NA + comp);
        out[b * 6 + tt * 2 + 0] = comp * (1.0f / NA);
        out[b * 6 + tt * 2 + 1] = b1 * (1.0f / NA);
    }
}

// ---------------- launch ----------------
extern "C" void kernel_launch(void* const* d_in, const int* in_sizes, int n_in,
                              void* d_out, int out_size) {
    const float* ret = (const float*)d_in[0];
    float* out = (float*)d_out;
    (void)in_sizes; (void)n_in; (void)out_size;

    cudaFuncSetAttribute(corr_mma_kernel,
                         cudaFuncAttributeMaxDynamicSharedMemorySize, SMEM_DYN);

    { dim3 g(NA / 32, BATCH); convert_kernel<<<g, 512>>>(ret); }
    { dim3 g(NTILE, BATCH);   corr_mma_kernel<<<g, 256, SMEM_DYN>>>(); }
    betti_kernel<<<96, 512>>>(ret, out);
}

// round 14
// speedup vs baseline: 1.0779x; 1.0197x over previous
#include <cuda_runtime.h>
#include <cuda_bf16.h>
#include <cstdint>

// B=32, W=256, N=512, thresholds {0.3,0.5,0.7}
// out: (B,6) fp32 [t0_b0,t0_b1,t1_b0,t1_b1,t2_b0,t2_b1]

#define BATCH 32
#define WIN   256
#define NA    512
#define CAP   131072   // >= 512*511/2
#define KCH   64       // bf16 per K-chunk (128 B rows)
#define NCH   4        // K = 256 (h.h only; band+fixup covers the bf16 error)
#define NSTG  3
#define STAGE_BYTES 24576   // 16KB A(128 rows) + 8KB B(64 rows)
#define SMEM_DYN    (NSTG * STAGE_BYTES)
#define NTILE 20
#define BAND  4.5e-3f       // certified |corr_exact - corr_hh| bound is 3.9e-3
#define SCAP  32768

// ---------------- device scratch ----------------
__device__ __nv_bfloat16 g_h[BATCH][NA][WIN];   // 8 MB
__device__ int   g_ecnt[3][BATCH];
__device__ unsigned int g_edges[3][BATCH][CAP];
__device__ int   g_scnt;
__device__ unsigned int g_susp[SCAP];   // (mask<<23)|(b<<18)|(gi<<9)|gj

__device__ __forceinline__ uint32_t smem_u32(const void* p) {
    uint32_t a;
    asm("{ .reg .u64 t; cvta.to.shared.u64 t, %1; cvt.u32.u64 %0, t; }" : "=r"(a) : "l"(p));
    return a;
}
#define SW128(x) ((x) ^ (((x) >> 3) & 0x70))
#define CP16(dst, src) \
    asm volatile("cp.async.cg.shared.global [%0], [%1], 16;" :: "r"(dst), "l"(src))
#define CPCOMMIT() asm volatile("cp.async.commit_group;" ::: "memory")
#define CPWAIT1()  asm volatile("cp.async.wait_group 1;" ::: "memory")
#define CPWAIT0()  asm volatile("cp.async.wait_group 0;" ::: "memory")

// ------- fused stats + normalize + bf16(h) + transpose (one smem pass) -------
// CTA: 32 assets x 256 w. grid (16, 32). 512 threads: a = t&31, q = t>>5.
// fsm unpadded [256][32]: column reads are conflict-free (row stride 128B).
__global__ void __launch_bounds__(512)
convert_kernel(const float* __restrict__ ret) {
    __shared__ __align__(16) float fsm[WIN][32];   // 32 KB
    __shared__ float ps[16][32], ps2[16][32], mean_s[32], inv_s[32];

    const int b = blockIdx.y, n0 = blockIdx.x * 32;
    const int t = threadIdx.x;

    if (blockIdx.x == 0 && b == 0) {
        if (t < 96) ((int*)g_ecnt)[t] = 0;
        if (t == 96) g_scnt = 0;
    }

    // phase 0: cp.async 256 w-rows x 128B segments into smem (no reg roundtrip)
    const float* src = ret + (size_t)b * WIN * NA + n0;
    const uint32_t sbase = smem_u32(fsm);
#pragma unroll
    for (int it = 0; it < 4; it++) {
        int idx = t + it * 512;
        int w = idx >> 3, sg = idx & 7;
        CP16(sbase + w * 128 + sg * 16, src + (size_t)w * NA + sg * 4);
    }
    CPCOMMIT();
    CPWAIT0();
    __syncthreads();

    // phase 1: read 16 column values once into registers; partial sums
    const int a = t & 31, q = t >> 5;     // q: 0..15 (16-w chunk)
    float x[16];
    {
        float s = 0.f, s2 = 0.f;
#pragma unroll
        for (int i = 0; i < 16; i++) {
            x[i] = fsm[q * 16 + i][a];
            s += x[i]; s2 += x[i] * x[i];
        }
        ps[q][a] = s; ps2[q][a] = s2;
    }
    __syncthreads();

    // phase 2: combine partials (fixed ascending order), stats
    if (q == 0) {
        float ss = 0.f, ss2 = 0.f;
#pragma unroll
        for (int k = 0; k < 16; k++) { ss += ps[k][a]; ss2 += ps2[k][a]; }
        float mean = ss * (1.0f / WIN);
        float var = fmaxf((ss2 - ss * mean) * (1.0f / (WIN - 1)), 0.0f);
        mean_s[a] = mean;
        inv_s[a] = 1.0f / (sqrtf(var) + 1e-8f);
    }
    __syncthreads();

    // phase 3: convert the same registers, store 32B per thread
    {
        const float mean = mean_s[a], inv = inv_s[a];
        unsigned int hw[8];
#pragma unroll
        for (int k = 0; k < 8; k++) {
            float x0 = (x[2 * k] - mean) * inv;
            float x1 = (x[2 * k + 1] - mean) * inv;
            __nv_bfloat16 h0 = __float2bfloat16(x0);
            __nv_bfloat16 h1 = __float2bfloat16(x1);
            hw[k] = ((unsigned int)__bfloat16_as_ushort(h1) << 16)
                  | __bfloat16_as_ushort(h0);
        }
        __nv_bfloat16* dh = &g_h[b][n0 + a][q * 16];
        *(uint4*)(dh + 0) = make_uint4(hw[0], hw[1], hw[2], hw[3]);
        *(uint4*)(dh + 8) = make_uint4(hw[4], hw[5], hw[6], hw[7]);
    }
}

// ---------------- corr GEMM: h.h via mma.sync bf16, K=256, 3-stage cp.async --
// CTA tile 128x64, 8 warps (4x2), warp tile 32x32. Grid: 20 upper-tri tiles x 32 b.
__global__ void __launch_bounds__(256, 3)
corr_mma_kernel() {
    extern __shared__ __align__(128) unsigned char dsm[];
    const uint32_t sb = smem_u32(dsm);

    const int TI[NTILE] = {0,0,0,0,0,0,0,0, 1,1,1,1,1,1, 2,2,2,2, 3,3};
    const int TJ[NTILE] = {0,1,2,3,4,5,6,7, 2,3,4,5,6,7, 4,5,6,7, 6,7};
    const int b  = blockIdx.y;
    const int i0 = TI[blockIdx.x] * 128;
    const int j0 = TJ[blockIdx.x] * 64;
    const int t = threadIdx.x;
    const int wid = t >> 5, lane = t & 31;
    const int mw = wid >> 1;       // 0..3 : 32-row group
    const int nw = wid & 1;        // 0..1 : 32-col group

    float acc[2][4][4];
#pragma unroll
    for (int mt = 0; mt < 2; mt++)
#pragma unroll
        for (int nt = 0; nt < 4; nt++)
#pragma unroll
            for (int q = 0; q < 4; q++) acc[mt][nt][q] = 0.f;

    const int arow = t >> 1, ahalf = t & 1;
    const uint32_t aswz = SW128(arow * 128 + ahalf * 64);
    const int brow = t >> 2, bq = t & 3;
    const uint32_t bswz = SW128(brow * 128 + bq * 32);

    const __nv_bfloat16* rowA = &g_h[b][i0 + arow][0];
    const __nv_bfloat16* rowB = &g_h[b][j0 + brow][0];

    auto load_chunk = [&](int c) {
        const uint32_t base = sb + (c % NSTG) * STAGE_BYTES;
        const __nv_bfloat16* sA = rowA + c * KCH + ahalf * 32;
#pragma unroll
        for (int f = 0; f < 4; f++)
            CP16(base + (aswz ^ (f * 16)), sA + f * 8);
        const __nv_bfloat16* sB = rowB + c * KCH + bq * 16;
        CP16(base + 16384 + bswz, sB);
        CP16(base + 16384 + (bswz ^ 16), sB + 8);
        CPCOMMIT();
    };

    load_chunk(0);
    load_chunk(1);

    for (int c = 0; c < NCH; c++) {
        if (c < NCH - 1) CPWAIT1(); else CPWAIT0();
        __syncthreads();

        const uint32_t sbA = sb + (c % NSTG) * STAGE_BYTES;
        const uint32_t sbB = sbA + 16384;
#pragma unroll
        for (int ks = 0; ks < 4; ks++) {
            const int kb = ks * 32;
            uint32_t af[2][4];
#pragma unroll
            for (int mt = 0; mt < 2; mt++) {
                int row = mw * 32 + mt * 16 + ((lane >> 3) & 1) * 8 + (lane & 7);
                int kbyte = kb + (lane >> 4) * 16;
                uint32_t addr = sbA + SW128(row * 128 + kbyte);
                asm volatile("ldmatrix.sync.aligned.m8n8.x4.shared.b16 {%0,%1,%2,%3}, [%4];"
                    : "=r"(af[mt][0]), "=r"(af[mt][1]), "=r"(af[mt][2]), "=r"(af[mt][3])
                    : "r"(addr));
            }
            uint32_t bf[4][2];
#pragma unroll
            for (int np = 0; np < 2; np++) {
                int row = nw * 32 + np * 16 + ((lane >> 4) & 1) * 8 + (lane & 7);
                int kbyte = kb + ((lane >> 3) & 1) * 16;
                uint32_t addr = sbB + SW128(row * 128 + kbyte);
                asm volatile("ldmatrix.sync.aligned.m8n8.x4.shared.b16 {%0,%1,%2,%3}, [%4];"
                    : "=r"(bf[2*np][0]), "=r"(bf[2*np][1]),
                      "=r"(bf[2*np+1][0]), "=r"(bf[2*np+1][1])
                    : "r"(addr));
            }
#pragma unroll
            for (int mt = 0; mt < 2; mt++)
#pragma unroll
                for (int nt = 0; nt < 4; nt++)
                    asm volatile(
                        "mma.sync.aligned.m16n8k16.row.col.f32.bf16.bf16.f32 "
                        "{%0,%1,%2,%3}, {%4,%5,%6,%7}, {%8,%9}, {%0,%1,%2,%3};"
                        : "+f"(acc[mt][nt][0]), "+f"(acc[mt][nt][1]),
                          "+f"(acc[mt][nt][2]), "+f"(acc[mt][nt][3])
                        : "r"(af[mt][0]), "r"(af[mt][1]), "r"(af[mt][2]), "r"(af[mt][3]),
                          "r"(bf[nt][0]), "r"(bf[nt][1]));
        }

        if (c + 2 < NCH) load_chunk(c + 2);
        else CPCOMMIT();   // keep group accounting uniform
    }

    // epilogue: banded threshold -> edges / suspects
    const float TH[3] = {0.3f, 0.5f, 0.7f};
#pragma unroll
    for (int mt = 0; mt < 2; mt++) {
#pragma unroll
        for (int nt = 0; nt < 4; nt++) {
            int gi0 = i0 + mw * 32 + mt * 16 + (lane >> 2);
            int gj0 = j0 + nw * 32 + nt * 8 + 2 * (lane & 3);
#pragma unroll
            for (int q = 0; q < 4; q++) {
                int gi = gi0 + (q >> 1) * 8;
                int gj = gj0 + (q & 1);
                float v = fabsf(acc[mt][nt][q] * (1.0f / 256.0f));
                if (gi < gj && v > TH[0] - BAND) {
                    unsigned int e = ((unsigned int)gi << 16) | (unsigned int)gj;
                    unsigned int mask = 0;
#pragma unroll
                    for (int k = 0; k < 3; k++) {
                        if (v > TH[k] + BAND) {
                            int p = atomicAdd(&g_ecnt[k][b], 1);
                            g_edges[k][b][p] = e;
                        } else if (v > TH[k] - BAND) {
                            mask |= 1u << k;
                        }
                    }
                    if (mask) {
                        int p = atomicAdd(&g_scnt, 1);
                        if (p < SCAP)
                            g_susp[p] = (mask << 23) | ((unsigned int)b << 18)
                                      | ((unsigned int)gi << 9) | (unsigned int)gj;
                    }
                }
            }
        }
    }
}

// ------- components + Betti, with in-block fp64 fixup of in-band suspects ----
__global__ void __launch_bounds__(512, 1)
betti_kernel(const float* __restrict__ ret, float* __restrict__ out) {
    __shared__ int label[NA];
    __shared__ int changed;
    __shared__ int comp_cnt;
    __shared__ unsigned int extra[512];
    __shared__ int extra_cnt;
    __shared__ double wsum[8][5];

    const int tt = blockIdx.x >> 5;
    const int b  = blockIdx.x & 31;
    const int tid = threadIdx.x;

    const int cnt = g_ecnt[tt][b];
    const unsigned int* el = &g_edges[tt][b][0];

    label[tid] = tid;
    if (tid == 0) { comp_cnt = 0; extra_cnt = 0; }
    __syncthreads();

    // resolve suspects for this (tt, b) with exact fp64 correlation
    const int scnt = min(g_scnt, SCAP);
    const double THD[3] = {0.3, 0.5, 0.7};
    for (int s = 0; s < scnt; s++) {
        unsigned int wd = g_susp[s];
        if ((((wd >> 18) & 31) != (unsigned)b) || !((wd >> 23) & (1u << tt)))
            continue;
        int gj = wd & 511, gi = (wd >> 9) & 511;

        double p0 = 0, p1 = 0, p2 = 0, p3 = 0, p4 = 0;
        if (tid < WIN) {
            double xi = (double)ret[((size_t)b * WIN + tid) * NA + gi];
            double xj = (double)ret[((size_t)b * WIN + tid) * NA + gj];
            p0 = xi; p1 = xi * xi; p2 = xj; p3 = xj * xj; p4 = xi * xj;
        }
#pragma unroll
        for (int o = 16; o; o >>= 1) {
            p0 += __shfl_down_sync(0xFFFFFFFFu, p0, o);
            p1 += __shfl_down_sync(0xFFFFFFFFu, p1, o);
            p2 += __shfl_down_sync(0xFFFFFFFFu, p2, o);
            p3 += __shfl_down_sync(0xFFFFFFFFu, p3, o);
            p4 += __shfl_down_sync(0xFFFFFFFFu, p4, o);
        }
        if (tid < WIN && (tid & 31) == 0) {
            wsum[tid >> 5][0] = p0; wsum[tid >> 5][1] = p1;
            wsum[tid >> 5][2] = p2; wsum[tid >> 5][3] = p3;
            wsum[tid >> 5][4] = p4;
        }
        __syncthreads();
        if (tid == 0) {
            double r0 = 0, r1 = 0, r2 = 0, r3 = 0, r4 = 0;
#pragma unroll
            for (int k = 0; k < 8; k++) {
                r0 += wsum[k][0]; r1 += wsum[k][1]; r2 += wsum[k][2];
                r3 += wsum[k][3]; r4 += wsum[k][4];
            }
            double mi = r0 / 256.0, mj = r2 / 256.0;
            double vi = (r1 - r0 * mi) / 255.0;
            double vj = (r3 - r2 * mj) / 255.0;
            double di = sqrt(vi > 0 ? vi : 0) + 1e-8;
            double dj = sqrt(vj > 0 ? vj : 0) + 1e-8;
            double cov = r4 - 256.0 * mi * mj;
            double v = fabs(cov / (di * dj) / 256.0);
            if (v > THD[tt] && extra_cnt < 512)
                extra[extra_cnt++] = ((unsigned int)gi << 16) | (unsigned int)gj;
        }
        __syncthreads();
    }

    // min-label propagation over main + extra edge lists
    while (true) {
        __syncthreads();
        if (tid == 0) changed = 0;
        __syncthreads();
        for (int e = tid; e < cnt; e += NA) {
            unsigned int pk = el[e];
            int i = pk >> 16, j = pk & 0xFFFF;
            int li = label[i], lj = label[j];
            if (li < lj) { atomicMin(&label[j], li); changed = 1; }
            else if (lj < li) { atomicMin(&label[i], lj); changed = 1; }
        }
        for (int e = tid; e < extra_cnt; e += NA) {
            unsigned int pk = extra[e];
            int i = pk >> 16, j = pk & 0xFFFF;
            int li = label[i], lj = label[j];
            if (li < lj) { atomicMin(&label[j], li); changed = 1; }
            else if (lj < li) { atomicMin(&label[i], lj); changed = 1; }
        }
        __syncthreads();
        int l = label[tid];
        int ll = label[l];
        if (ll < l) { label[tid] = ll; changed = 1; }
        __syncthreads();
        if (!changed) break;
    }

    int isrep = (label[tid] == tid) ? 1 : 0;
#pragma unroll
    for (int o = 16; o; o >>= 1) isrep += __shfl_down_sync(0xFFFFFFFFu, isrep, o);
    if ((tid & 31) == 0) atomicAdd(&comp_cnt, isrep);
    __syncthreads();

    if (tid == 0) {
        float comp = (float)comp_cnt;
        float edges = (float)(cnt + extra_cnt);
        float b1 = fmaxf(0.0f, edges - (float)NA + comp);
        out[b * 6 + tt * 2 + 0] = comp * (1.0f / NA);
        out[b * 6 + tt * 2 + 1] = b1 * (1.0f / NA);
    }
}

// ---------------- launch ----------------
extern "C" void kernel_launch(void* const* d_in, const int* in_sizes, int n_in,
                              void* d_out, int out_size) {
    const float* ret = (const float*)d_in[0];
    float* out = (float*)d_out;
    (void)in_sizes; (void)n_in; (void)out_size;

    cudaFuncSetAttribute(corr_mma_kernel,
                         cudaFuncAttributeMaxDynamicSharedMemorySize, SMEM_DYN);

    { dim3 g(NA / 32, BATCH); convert_kernel<<<g, 512>>>(ret); }
    { dim3 g(NTILE, BATCH);   corr_mma_kernel<<<g, 256, SMEM_DYN>>>(); }
    betti_kernel<<<96, 512>>>(ret, out);
}